// round 1
// baseline (speedup 1.0000x reference)
#include <cuda_runtime.h>

#define N_NODES 50000
#define N_EDGES 800000
#define HID 64
#define HEADS 4

// ---------------- scratch (static device globals; no allocation) ----------------
__device__ int   g_is64;
__device__ int   g_src[N_EDGES];
__device__ int   g_dst[N_EDGES];
__device__ float g_x[N_NODES * HEADS * HID];     // 51.2 MB
__device__ float g_asrc[N_NODES * HEADS];
__device__ float g_adst[N_NODES * HEADS];
__device__ float g_amax[N_NODES * HEADS];
__device__ float g_esum[N_NODES * HEADS];
__device__ float g_alpha[N_EDGES * HEADS];       // 12.8 MB
__device__ float g_v[12];                        // [edim][head]

// ---------------- dtype sniffer: int64 vs int32 edge_index ----------------
__global__ void k_detect(const unsigned* __restrict__ p) {
    __shared__ int bad;
    if (threadIdx.x == 0) bad = 0;
    __syncthreads();
    unsigned acc = 0;
#pragma unroll
    for (int i = 0; i < 4; i++) acc |= p[2 * (threadIdx.x * 4 + i) + 1];
    if (acc) atomicOr(&bad, 1);
    __syncthreads();
    if (threadIdx.x == 0) g_is64 = bad ? 0 : 1;
}

__global__ void k_unpack(const void* __restrict__ p) {
    int e = blockIdx.x * blockDim.x + threadIdx.x;
    if (e >= N_EDGES) return;
    if (g_is64) {
        const long long* q = (const long long*)p;
        g_src[e] = (int)q[e];
        g_dst[e] = (int)q[N_EDGES + e];
    } else {
        const int* q = (const int*)p;
        g_src[e] = q[e];
        g_dst[e] = q[N_EDGES + e];
    }
}

// ---------------- init: zero output accumulator, amax=-inf, esum=0 ----------------
__global__ void k_init(float* __restrict__ out) {
    int i = blockIdx.x * blockDim.x + threadIdx.x;
    if (i < N_NODES * HID) out[i] = 0.0f;
    if (i < N_NODES * HEADS) {
        g_amax[i] = __int_as_float(0xff800000); // -inf
        g_esum[i] = 0.0f;
    }
}

// ---------------- x = h @ W  (N x 64  @  64 x 256) ----------------
// 16 nodes per block, 256 threads (one output column each).
__global__ void k_gemm(const float* __restrict__ h, const float* __restrict__ W) {
    __shared__ float hs[64][16];
    int t = threadIdx.x;
    int n0 = blockIdx.x * 16;
    for (int idx = t; idx < 1024; idx += 256) {
        int ni = idx >> 6, k = idx & 63;
        hs[k][ni] = h[(n0 + ni) * 64 + k];
    }
    __syncthreads();
    float acc[16];
#pragma unroll
    for (int i = 0; i < 16; i++) acc[i] = 0.0f;
#pragma unroll 4
    for (int k = 0; k < 64; k++) {
        float w = W[k * 256 + t];
#pragma unroll
        for (int q = 0; q < 4; q++) {
            float4 hv = *(const float4*)&hs[k][q * 4];
            acc[q * 4 + 0] += hv.x * w;
            acc[q * 4 + 1] += hv.y * w;
            acc[q * 4 + 2] += hv.z * w;
            acc[q * 4 + 3] += hv.w * w;
        }
    }
#pragma unroll
    for (int ni = 0; ni < 16; ni++)
        g_x[(n0 + ni) * 256 + t] = acc[ni];
}

// ---------------- a_src / a_dst per node ----------------
__global__ void k_attn(const float* __restrict__ att_src, const float* __restrict__ att_dst) {
    int n = blockIdx.x, t = threadIdx.x;
    float v = g_x[n * 256 + t];
    float s = v * att_src[t];
    float d = v * att_dst[t];
#pragma unroll
    for (int o = 16; o; o >>= 1) {
        s += __shfl_xor_sync(0xffffffffu, s, o);
        d += __shfl_xor_sync(0xffffffffu, d, o);
    }
    __shared__ float ss[8], sd[8];
    int w = t >> 5;
    if ((t & 31) == 0) { ss[w] = s; sd[w] = d; }
    __syncthreads();
    if (t < 4) {
        g_asrc[n * 4 + t] = ss[2 * t] + ss[2 * t + 1];
        g_adst[n * 4 + t] = sd[2 * t] + sd[2 * t + 1];
    }
}

// ---------------- v[d][h] = sum_c W_edge[d, h*64+c] * att_edge[h,c] ----------------
__global__ void k_vedge(const float* __restrict__ W_edge, const float* __restrict__ att_edge) {
    int t = threadIdx.x;
    if (t < 12) {
        int d = t >> 2, h = t & 3;
        float s = 0.0f;
        for (int c = 0; c < 64; c++)
            s += W_edge[d * 256 + h * 64 + c] * att_edge[h * 64 + c];
        g_v[t] = s; // layout [d*4 + h]
    }
}

__device__ __forceinline__ void atomicMaxF(float* a, float v) {
    if (v >= 0.0f) atomicMax((int*)a, __float_as_int(v));
    else           atomicMin((unsigned int*)a, __float_as_uint(v));
}

// ---------------- pass A: alpha = leakyrelu(...) ; segment max ----------------
__global__ void k_passA(const float* __restrict__ attr) {
    int e = blockIdx.x * blockDim.x + threadIdx.x;
    if (e >= N_EDGES) return;
    int s = g_src[e], d = g_dst[e];
    float a0 = attr[e * 3 + 0], a1 = attr[e * 3 + 1], a2 = attr[e * 3 + 2];
    float4 as = *(const float4*)&g_asrc[s * 4];
    float4 ad = *(const float4*)&g_adst[d * 4];
    float base[4] = {as.x + ad.x, as.y + ad.y, as.z + ad.z, as.w + ad.w};
    float4 outv;
    float* po = &outv.x;
#pragma unroll
    for (int h = 0; h < 4; h++) {
        float a = base[h] + a0 * g_v[h] + a1 * g_v[4 + h] + a2 * g_v[8 + h];
        a = a > 0.0f ? a : 0.2f * a;
        po[h] = a;
        atomicMaxF(&g_amax[d * 4 + h], a);
    }
    *(float4*)&g_alpha[e * 4] = outv;
}

// ---------------- pass B: exp(alpha - amax[dst]) ; segment sum ----------------
__global__ void k_passB() {
    int e = blockIdx.x * blockDim.x + threadIdx.x;
    if (e >= N_EDGES) return;
    int d = g_dst[e];
    float4 al = *(const float4*)&g_alpha[e * 4];
    float4 mx = *(const float4*)&g_amax[d * 4];
    float4 ex;
    ex.x = expf(al.x - mx.x);
    ex.y = expf(al.y - mx.y);
    ex.z = expf(al.z - mx.z);
    ex.w = expf(al.w - mx.w);
    *(float4*)&g_alpha[e * 4] = ex;
    atomicAdd((float4*)&g_esum[d * 4], ex);
}

// ---------------- pass C: out[dst] += mean_h( alpha_h * x[src,h,:] ) ----------------
// 16 lanes per edge; lane j handles channels 4j..4j+3 (float4). 2 edges/warp, 16 edges/block.
__global__ void k_passC(float* __restrict__ out) {
    int t = threadIdx.x;
    int lane = t & 31, warp = t >> 5;
    int e = blockIdx.x * 16 + warp * 2 + (lane >> 4);
    int j = lane & 15;
    int s = g_src[e], d = g_dst[e];
    float4 ex = *(const float4*)&g_alpha[e * 4];
    float4 es = *(const float4*)&g_esum[d * 4];
    float w0 = ex.x * 0.25f / (es.x + 1e-16f);
    float w1 = ex.y * 0.25f / (es.y + 1e-16f);
    float w2 = ex.z * 0.25f / (es.z + 1e-16f);
    float w3 = ex.w * 0.25f / (es.w + 1e-16f);
    const float4* xp = (const float4*)&g_x[s * 256];
    float4 x0 = xp[j];
    float4 x1 = xp[16 + j];
    float4 x2 = xp[32 + j];
    float4 x3 = xp[48 + j];
    float4 acc;
    acc.x = w0 * x0.x + w1 * x1.x + w2 * x2.x + w3 * x3.x;
    acc.y = w0 * x0.y + w1 * x1.y + w2 * x2.y + w3 * x3.y;
    acc.z = w0 * x0.z + w1 * x1.z + w2 * x2.z + w3 * x3.z;
    acc.w = w0 * x0.w + w1 * x1.w + w2 * x2.w + w3 * x3.w;
    atomicAdd((float4*)out + (d * 16 + j), acc);
}

// ---------------- final: (+bias) LayerNorm + SiLU, in place on d_out ----------------
__global__ void k_final(float* __restrict__ out, const float* __restrict__ bias,
                        const float* __restrict__ gamma, const float* __restrict__ beta) {
    int t = threadIdx.x;
    int lane = t & 31, warp = t >> 5;
    int n = blockIdx.x * 8 + warp;
    float v0 = out[n * 64 + lane] + bias[lane];
    float v1 = out[n * 64 + 32 + lane] + bias[32 + lane];
    float sum = v0 + v1;
    float sq = v0 * v0 + v1 * v1;
#pragma unroll
    for (int o = 16; o; o >>= 1) {
        sum += __shfl_xor_sync(0xffffffffu, sum, o);
        sq  += __shfl_xor_sync(0xffffffffu, sq, o);
    }
    float mu = sum * (1.0f / 64.0f);
    float var = sq * (1.0f / 64.0f) - mu * mu;
    float inv = rsqrtf(var + 1e-5f);
    float y0 = (v0 - mu) * inv * gamma[lane] + beta[lane];
    float y1 = (v1 - mu) * inv * gamma[32 + lane] + beta[32 + lane];
    y0 = y0 / (1.0f + expf(-y0));
    y1 = y1 / (1.0f + expf(-y1));
    out[n * 64 + lane] = y0;
    out[n * 64 + 32 + lane] = y1;
}

extern "C" void kernel_launch(void* const* d_in, const int* in_sizes, int n_in,
                              void* d_out, int out_size) {
    // metadata order: t, h, edge_index, edge_attr, W, att_src, att_dst,
    //                 W_edge, att_edge, bias, ln_gamma, ln_beta
    const float* h        = (const float*)d_in[1];
    const void*  ei       = d_in[2];
    const float* attr     = (const float*)d_in[3];
    const float* W        = (const float*)d_in[4];
    const float* att_src  = (const float*)d_in[5];
    const float* att_dst  = (const float*)d_in[6];
    const float* W_edge   = (const float*)d_in[7];
    const float* att_edge = (const float*)d_in[8];
    const float* bias     = (const float*)d_in[9];
    const float* gamma    = (const float*)d_in[10];
    const float* beta     = (const float*)d_in[11];
    float* out = (float*)d_out;

    k_detect<<<1, 256>>>((const unsigned*)ei);
    k_unpack<<<(N_EDGES + 255) / 256, 256>>>(ei);
    k_init<<<(N_NODES * HID + 255) / 256, 256>>>(out);
    k_vedge<<<1, 32>>>(W_edge, att_edge);
    k_gemm<<<N_NODES / 16, 256>>>(h, W);
    k_attn<<<N_NODES, 256>>>(att_src, att_dst);
    k_passA<<<N_EDGES / 256, 256>>>(attr);
    k_passB<<<N_EDGES / 256, 256>>>();
    k_passC<<<N_EDGES / 16, 256>>>(out);
    k_final<<<N_NODES / 8, 256>>>(out, bias, gamma, beta);
}

// round 2
// speedup vs baseline: 1.1293x; 1.1293x over previous
#include <cuda_runtime.h>

#define N_NODES 50000
#define N_EDGES 800000
#define NB_SCAN 49          // ceil(50000/1024)

// ---------------- scratch (static device globals; no allocation) ----------------
__device__ int   g_is64;
__device__ int   g_src[N_EDGES];
__device__ int   g_dst[N_EDGES];
__device__ int   g_cnt[N_NODES];
__device__ int   g_scan[NB_SCAN * 1024];
__device__ int   g_btot[NB_SCAN];
__device__ int   g_boff[NB_SCAN];
__device__ int   g_off[N_NODES + 1];
__device__ int   g_cur[N_NODES];
__device__ int   g_ssrc[N_EDGES];
__device__ float g_salpha[N_EDGES * 4];          // sorted alpha, 12.8 MB
__device__ float g_x[N_NODES * 256];             // 51.2 MB
__device__ float g_asrc[N_NODES * 4];
__device__ float g_adst[N_NODES * 4];
__device__ float g_v[12];                        // [edim*4 + head]

// ---------------- zero the histogram (runs every replay!) ----------------
__global__ void k_init() {
    int i = blockIdx.x * blockDim.x + threadIdx.x;
    if (i < N_NODES) g_cnt[i] = 0;
    if (i == 0) g_off[N_NODES] = N_EDGES;
}

// ---------------- dtype sniffer: int64 vs int32 edge_index ----------------
__global__ void k_detect(const unsigned* __restrict__ p) {
    __shared__ int bad;
    if (threadIdx.x == 0) bad = 0;
    __syncthreads();
    unsigned acc = 0;
#pragma unroll
    for (int i = 0; i < 4; i++) acc |= p[2 * (threadIdx.x * 4 + i) + 1];
    if (acc) atomicOr(&bad, 1);
    __syncthreads();
    if (threadIdx.x == 0) g_is64 = bad ? 0 : 1;
}

// ---------------- unpack edge_index + dst histogram ----------------
__global__ void k_prep(const void* __restrict__ p) {
    int e = blockIdx.x * blockDim.x + threadIdx.x;
    if (e >= N_EDGES) return;
    int s, d;
    if (g_is64) {
        const long long* q = (const long long*)p;
        s = (int)q[e]; d = (int)q[N_EDGES + e];
    } else {
        const int* q = (const int*)p;
        s = q[e]; d = q[N_EDGES + e];
    }
    g_src[e] = s;
    g_dst[e] = d;
    atomicAdd(&g_cnt[d], 1);
}

// ---------------- 3-kernel block scan over g_cnt ----------------
__global__ void k_scan1() {
    __shared__ int s[1024];
    int b = blockIdx.x, t = threadIdx.x;
    int i = b * 1024 + t;
    int v = (i < N_NODES) ? g_cnt[i] : 0;
    s[t] = v;
    __syncthreads();
    for (int off = 1; off < 1024; off <<= 1) {
        int u = (t >= off) ? s[t - off] : 0;
        __syncthreads();
        s[t] += u;
        __syncthreads();
    }
    g_scan[i] = s[t];
    if (t == 1023) g_btot[b] = s[t];
}

__global__ void k_scan2() {
    __shared__ int s[64];
    int t = threadIdx.x;
    int v = (t < NB_SCAN) ? g_btot[t] : 0;
    s[t] = v;
    __syncthreads();
    for (int off = 1; off < 64; off <<= 1) {
        int u = (t >= off) ? s[t - off] : 0;
        __syncthreads();
        s[t] += u;
        __syncthreads();
    }
    if (t < NB_SCAN) g_boff[t] = s[t] - v;   // exclusive
}

__global__ void k_scan3() {
    int b = blockIdx.x, t = threadIdx.x;
    int i = b * 1024 + t;
    if (i >= N_NODES) return;
    int off = g_scan[i] - g_cnt[i] + g_boff[b]; // exclusive prefix
    g_off[i] = off;
    g_cur[i] = off;
}

// ---------------- v[d*4+h] = sum_c W_edge[d, h*64+c] * att_edge[h,c] ----------------
__global__ void k_vedge(const float* __restrict__ W_edge, const float* __restrict__ att_edge) {
    int t = threadIdx.x, lane = t & 31, w = t >> 5;  // 12 warps
    int d = w >> 2, h = w & 3;
    float s = W_edge[d * 256 + h * 64 + lane]      * att_edge[h * 64 + lane]
            + W_edge[d * 256 + h * 64 + 32 + lane] * att_edge[h * 64 + 32 + lane];
#pragma unroll
    for (int o = 16; o; o >>= 1) s += __shfl_xor_sync(0xffffffffu, s, o);
    if (lane == 0) g_v[w] = s;
}

// ---------------- x = h @ W  (N x 64 @ 64 x 256), 16 nodes/block ----------------
__global__ void k_gemm(const float* __restrict__ h, const float* __restrict__ W) {
    __shared__ float hs[64][16];
    int t = threadIdx.x;
    int n0 = blockIdx.x * 16;
    for (int idx = t; idx < 1024; idx += 256) {
        int ni = idx >> 6, k = idx & 63;
        hs[k][ni] = h[(n0 + ni) * 64 + k];
    }
    __syncthreads();
    float acc[16];
#pragma unroll
    for (int i = 0; i < 16; i++) acc[i] = 0.0f;
#pragma unroll 4
    for (int k = 0; k < 64; k++) {
        float w = W[k * 256 + t];
#pragma unroll
        for (int q = 0; q < 4; q++) {
            float4 hv = *(const float4*)&hs[k][q * 4];
            acc[q * 4 + 0] += hv.x * w;
            acc[q * 4 + 1] += hv.y * w;
            acc[q * 4 + 2] += hv.z * w;
            acc[q * 4 + 3] += hv.w * w;
        }
    }
#pragma unroll
    for (int ni = 0; ni < 16; ni++)
        g_x[(n0 + ni) * 256 + t] = acc[ni];
}

// ---------------- a_src/a_dst, warp per node ----------------
__global__ void k_attn(const float* __restrict__ att_src, const float* __restrict__ att_dst) {
    int t = threadIdx.x, lane = t & 31, w = t >> 5;
    int n = blockIdx.x * 8 + w;
    const float4* xp  = (const float4*)&g_x[n * 256];
    const float4* as4 = (const float4*)att_src;
    const float4* ad4 = (const float4*)att_dst;
    float4 v0 = xp[lane * 2], v1 = xp[lane * 2 + 1];
    float4 a0 = as4[lane * 2], a1 = as4[lane * 2 + 1];
    float4 b0 = ad4[lane * 2], b1 = ad4[lane * 2 + 1];
    float s = v0.x * a0.x + v0.y * a0.y + v0.z * a0.z + v0.w * a0.w
            + v1.x * a1.x + v1.y * a1.y + v1.z * a1.z + v1.w * a1.w;
    float d = v0.x * b0.x + v0.y * b0.y + v0.z * b0.z + v0.w * b0.w
            + v1.x * b1.x + v1.y * b1.y + v1.z * b1.z + v1.w * b1.w;
#pragma unroll
    for (int o = 4; o; o >>= 1) {   // reduce within 8-lane group (one head each)
        s += __shfl_xor_sync(0xffffffffu, s, o);
        d += __shfl_xor_sync(0xffffffffu, d, o);
    }
    int head = lane >> 3;
    if ((lane & 7) == 0) {
        g_asrc[n * 4 + head] = s;
        g_adst[n * 4 + head] = d;
    }
}

// ---------------- scatter (fused pass A): sorted {alpha4, src} per dst ----------------
__global__ void k_scatter(const float* __restrict__ attr) {
    int e = blockIdx.x * blockDim.x + threadIdx.x;
    if (e >= N_EDGES) return;
    int s = g_src[e], d = g_dst[e];
    float a0 = attr[e * 3 + 0], a1 = attr[e * 3 + 1], a2 = attr[e * 3 + 2];
    float4 as = *(const float4*)&g_asrc[s * 4];
    float4 ad = *(const float4*)&g_adst[d * 4];
    float base[4] = {as.x + ad.x, as.y + ad.y, as.z + ad.z, as.w + ad.w};
    float4 outv;
    float* po = &outv.x;
#pragma unroll
    for (int h = 0; h < 4; h++) {
        float a = base[h] + a0 * g_v[h] + a1 * g_v[4 + h] + a2 * g_v[8 + h];
        po[h] = a > 0.0f ? a : 0.2f * a;
    }
    int pos = atomicAdd(&g_cur[d], 1);
    *(float4*)&g_salpha[pos * 4] = outv;
    g_ssrc[pos] = s;
}

// ---------------- warp per node: softmax + weighted gather + LN + SiLU ----------------
__global__ void k_node(float* __restrict__ out, const float* __restrict__ bias,
                       const float* __restrict__ gamma, const float* __restrict__ beta) {
    int t = threadIdx.x, lane = t & 31, w = t >> 5;
    int n = blockIdx.x * 8 + w;
    int beg = g_off[n], end = g_off[n + 1];
    const float4* sal = (const float4*)g_salpha;

    // pass 1: segment max per head
    const float NINF = __int_as_float(0xff800000);
    float4 m = {NINF, NINF, NINF, NINF};
    for (int k = beg + lane; k < end; k += 32) {
        float4 a = sal[k];
        m.x = fmaxf(m.x, a.x); m.y = fmaxf(m.y, a.y);
        m.z = fmaxf(m.z, a.z); m.w = fmaxf(m.w, a.w);
    }
#pragma unroll
    for (int o = 16; o; o >>= 1) {
        m.x = fmaxf(m.x, __shfl_xor_sync(0xffffffffu, m.x, o));
        m.y = fmaxf(m.y, __shfl_xor_sync(0xffffffffu, m.y, o));
        m.z = fmaxf(m.z, __shfl_xor_sync(0xffffffffu, m.z, o));
        m.w = fmaxf(m.w, __shfl_xor_sync(0xffffffffu, m.w, o));
    }

    // pass 2: sum of exp
    float4 sm = {0.f, 0.f, 0.f, 0.f};
    for (int k = beg + lane; k < end; k += 32) {
        float4 a = sal[k];
        sm.x += expf(a.x - m.x); sm.y += expf(a.y - m.y);
        sm.z += expf(a.z - m.z); sm.w += expf(a.w - m.w);
    }
#pragma unroll
    for (int o = 16; o; o >>= 1) {
        sm.x += __shfl_xor_sync(0xffffffffu, sm.x, o);
        sm.y += __shfl_xor_sync(0xffffffffu, sm.y, o);
        sm.z += __shfl_xor_sync(0xffffffffu, sm.z, o);
        sm.w += __shfl_xor_sync(0xffffffffu, sm.w, o);
    }
    float i0 = 0.25f / (sm.x + 1e-16f);
    float i1 = 0.25f / (sm.y + 1e-16f);
    float i2 = 0.25f / (sm.z + 1e-16f);
    float i3 = 0.25f / (sm.w + 1e-16f);

    // pass 3: weighted gather-sum of x[src]
    // lane holds float4 at x[src*256 + r*128 + lane*4]; head = r*2 + (lane>=16)
    float4 acc0 = {0.f, 0.f, 0.f, 0.f}, acc1 = {0.f, 0.f, 0.f, 0.f};
    bool hi = lane >= 16;
    const float4* x4 = (const float4*)g_x;
    for (int k = beg; k < end; k++) {
        int s = g_ssrc[k];            // uniform
        float4 a = sal[k];            // uniform
        float w0 = expf(a.x - m.x) * i0;
        float w1 = expf(a.y - m.y) * i1;
        float w2 = expf(a.z - m.z) * i2;
        float w3 = expf(a.w - m.w) * i3;
        float wa = hi ? w1 : w0;
        float wb = hi ? w3 : w2;
        float4 xv0 = x4[s * 64 + lane];
        float4 xv1 = x4[s * 64 + 32 + lane];
        acc0.x += wa * xv0.x; acc0.y += wa * xv0.y;
        acc0.z += wa * xv0.z; acc0.w += wa * xv0.w;
        acc1.x += wb * xv1.x; acc1.y += wb * xv1.y;
        acc1.z += wb * xv1.z; acc1.w += wb * xv1.w;
    }
    // both rounds land on channels c = (lane&15)*4 .. +3
    float4 v;
    v.x = acc0.x + acc1.x; v.y = acc0.y + acc1.y;
    v.z = acc0.z + acc1.z; v.w = acc0.w + acc1.w;
    // fold lane j+16 into lane j (same channels, other heads)
    v.x += __shfl_xor_sync(0xffffffffu, v.x, 16);
    v.y += __shfl_xor_sync(0xffffffffu, v.y, 16);
    v.z += __shfl_xor_sync(0xffffffffu, v.z, 16);
    v.w += __shfl_xor_sync(0xffffffffu, v.w, 16);

    // lanes 0..15 hold out[n, 4*lane .. 4*lane+3]; fused +bias, LN, SiLU
    int j = lane & 15;
    float4 b4 = ((const float4*)bias)[j];
    v.x += b4.x; v.y += b4.y; v.z += b4.z; v.w += b4.w;
    float sum = v.x + v.y + v.z + v.w;
    float sq  = v.x * v.x + v.y * v.y + v.z * v.z + v.w * v.w;
#pragma unroll
    for (int o = 8; o; o >>= 1) {   // reduce within 16-lane group
        sum += __shfl_xor_sync(0xffffffffu, sum, o);
        sq  += __shfl_xor_sync(0xffffffffu, sq, o);
    }
    float mu  = sum * (1.0f / 64.0f);
    float var = sq * (1.0f / 64.0f) - mu * mu;
    float inv = rsqrtf(var + 1e-5f);
    float4 g4 = ((const float4*)gamma)[j];
    float4 be4 = ((const float4*)beta)[j];
    float4 y;
    y.x = (v.x - mu) * inv * g4.x + be4.x;
    y.y = (v.y - mu) * inv * g4.y + be4.y;
    y.z = (v.z - mu) * inv * g4.z + be4.z;
    y.w = (v.w - mu) * inv * g4.w + be4.w;
    y.x = y.x / (1.0f + expf(-y.x));
    y.y = y.y / (1.0f + expf(-y.y));
    y.z = y.z / (1.0f + expf(-y.z));
    y.w = y.w / (1.0f + expf(-y.w));
    if (lane < 16)
        ((float4*)out)[n * 16 + j] = y;
}

extern "C" void kernel_launch(void* const* d_in, const int* in_sizes, int n_in,
                              void* d_out, int out_size) {
    // order: t, h, edge_index, edge_attr, W, att_src, att_dst,
    //        W_edge, att_edge, bias, ln_gamma, ln_beta
    const float* h        = (const float*)d_in[1];
    const void*  ei       = d_in[2];
    const float* attr     = (const float*)d_in[3];
    const float* W        = (const float*)d_in[4];
    const float* att_src  = (const float*)d_in[5];
    const float* att_dst  = (const float*)d_in[6];
    const float* W_edge   = (const float*)d_in[7];
    const float* att_edge = (const float*)d_in[8];
    const float* bias     = (const float*)d_in[9];
    const float* gamma    = (const float*)d_in[10];
    const float* beta     = (const float*)d_in[11];
    float* out = (float*)d_out;

    k_init   <<<(N_NODES + 255) / 256, 256>>>();
    k_detect <<<1, 256>>>((const unsigned*)ei);
    k_prep   <<<(N_EDGES + 255) / 256, 256>>>(ei);
    k_scan1  <<<NB_SCAN, 1024>>>();
    k_scan2  <<<1, 64>>>();
    k_scan3  <<<NB_SCAN, 1024>>>();
    k_vedge  <<<1, 384>>>(W_edge, att_edge);
    k_gemm   <<<N_NODES / 16, 256>>>(h, W);
    k_attn   <<<N_NODES / 8, 256>>>(att_src, att_dst);
    k_scatter<<<(N_EDGES + 255) / 256, 256>>>(attr);
    k_node   <<<N_NODES / 8, 256>>>(out, bias, gamma, beta);
}

// round 3
// speedup vs baseline: 1.7283x; 1.5305x over previous
#include <cuda_runtime.h>
#include <cuda_fp16.h>

#define N_NODES 50000
#define N_EDGES 800000
#define NB_SCAN 49          // ceil(50000/1024)

// ---------------- scratch (static device globals; no allocation) ----------------
__device__ int   g_is64;
__device__ __align__(16) int   g_src[N_EDGES];
__device__ __align__(16) int   g_dst[N_EDGES];
__device__ int   g_cnt[N_NODES];
__device__ int   g_scan[NB_SCAN * 1024];
__device__ int   g_btot[NB_SCAN];
__device__ int   g_boff[NB_SCAN];
__device__ int   g_off[N_NODES + 1];
__device__ int   g_cur[N_NODES];
__device__ __align__(16) int    g_ssrc[N_EDGES];
__device__ __align__(16) float  g_salpha[N_EDGES * 4];     // 12.8 MB
__device__ __align__(16) __half2 g_x2[N_NODES * 128];      // x in fp16, 25.6 MB
__device__ __align__(16) float  g_asrc[N_NODES * 4];
__device__ __align__(16) float  g_adst[N_NODES * 4];
__device__ __align__(16) __half g_WhT[256 * 64];           // W transposed [n][k], fp16
__device__ float g_v[12];                                  // [edim*4 + head]

// ---------------- init: zero histogram + dtype sniffer ----------------
__global__ void k_init(const unsigned* __restrict__ p) {
    if (blockIdx.x < 196) {
        int i = blockIdx.x * 256 + threadIdx.x;
        if (i < N_NODES) g_cnt[i] = 0;
        if (blockIdx.x == 0 && threadIdx.x == 0) g_off[N_NODES] = N_EDGES;
    } else {
        __shared__ int bad;
        if (threadIdx.x == 0) bad = 0;
        __syncthreads();
        unsigned acc = 0;
#pragma unroll
        for (int i = 0; i < 4; i++) acc |= p[2 * (threadIdx.x * 4 + i) + 1];
        if (acc) atomicOr(&bad, 1);
        __syncthreads();
        if (threadIdx.x == 0) g_is64 = bad ? 0 : 1;
    }
}

// ---------------- unpack edge_index + dst histogram ----------------
__global__ void k_prep(const void* __restrict__ p) {
    int e = blockIdx.x * blockDim.x + threadIdx.x;
    if (e >= N_EDGES) return;
    int s, d;
    if (g_is64) {
        const long long* q = (const long long*)p;
        s = (int)q[e]; d = (int)q[N_EDGES + e];
    } else {
        const int* q = (const int*)p;
        s = q[e]; d = q[N_EDGES + e];
    }
    g_src[e] = s;
    g_dst[e] = d;
    atomicAdd(&g_cnt[d], 1);
}

// ---------------- 3-kernel block scan over g_cnt ----------------
__global__ void k_scan1() {
    __shared__ int s[1024];
    int b = blockIdx.x, t = threadIdx.x;
    int i = b * 1024 + t;
    int v = (i < N_NODES) ? g_cnt[i] : 0;
    s[t] = v;
    __syncthreads();
    for (int off = 1; off < 1024; off <<= 1) {
        int u = (t >= off) ? s[t - off] : 0;
        __syncthreads();
        s[t] += u;
        __syncthreads();
    }
    g_scan[i] = s[t];
    if (t == 1023) g_btot[b] = s[t];
}

__global__ void k_scan2() {
    __shared__ int s[64];
    int t = threadIdx.x;
    int v = (t < NB_SCAN) ? g_btot[t] : 0;
    s[t] = v;
    __syncthreads();
    for (int off = 1; off < 64; off <<= 1) {
        int u = (t >= off) ? s[t - off] : 0;
        __syncthreads();
        s[t] += u;
        __syncthreads();
    }
    if (t < NB_SCAN) g_boff[t] = s[t] - v;   // exclusive
}

__global__ void k_scan3() {
    int b = blockIdx.x, t = threadIdx.x;
    int i = b * 1024 + t;
    if (i >= N_NODES) return;
    int off = g_scan[i] - g_cnt[i] + g_boff[b]; // exclusive prefix
    g_off[i] = off;
    g_cur[i] = off;
}

// ---------------- W transpose->fp16, plus v_edge reduction ----------------
__global__ void k_wconv(const float* __restrict__ W, const float* __restrict__ W_edge,
                        const float* __restrict__ att_edge) {
    if (blockIdx.x < 64) {
        int j = blockIdx.x * 256 + threadIdx.x;   // j = n*64 + k
        int n = j >> 6, k = j & 63;
        g_WhT[j] = __float2half(W[k * 256 + n]);
    } else {
        int t = threadIdx.x;
        if (t < 192) {
            int pair = t >> 4, l = t & 15;        // pair = d*4 + h
            int d = pair >> 2, hh = pair & 3;
            float s = 0.0f;
#pragma unroll
            for (int q = 0; q < 4; q++)
                s += W_edge[d * 256 + hh * 64 + l + 16 * q] * att_edge[hh * 64 + l + 16 * q];
            s += __shfl_xor_sync(0xffffffffu, s, 8);
            s += __shfl_xor_sync(0xffffffffu, s, 4);
            s += __shfl_xor_sync(0xffffffffu, s, 2);
            s += __shfl_xor_sync(0xffffffffu, s, 1);
            if (l == 0) g_v[pair] = s;
        }
    }
}

// ---------------- tensor-core GEMM x = h @ W, fused a_src/a_dst ----------------
__device__ __forceinline__ void mma16816(float* c, unsigned a0, unsigned a1, unsigned a2,
                                         unsigned a3, unsigned b0, unsigned b1) {
    asm volatile(
        "mma.sync.aligned.m16n8k16.row.col.f32.f16.f16.f32 "
        "{%0,%1,%2,%3},{%4,%5,%6,%7},{%8,%9},{%0,%1,%2,%3};\n"
        : "+f"(c[0]), "+f"(c[1]), "+f"(c[2]), "+f"(c[3])
        : "r"(a0), "r"(a1), "r"(a2), "r"(a3), "r"(b0), "r"(b1));
}

__global__ void __launch_bounds__(256) k_gemm(const float* __restrict__ h,
                                              const float* __restrict__ att_src,
                                              const float* __restrict__ att_dst) {
    __shared__ __half As[32 * 72];    // 32 rows x 64 k, pitch 72
    __shared__ __half Ws[256 * 72];   // 256 n x 64 k, pitch 72
    int t = threadIdx.x, lane = t & 31, w = t >> 5;
    int n0 = blockIdx.x * 32;

    // load W^T (fp16) into smem, vectorized
#pragma unroll
    for (int q = 0; q < 8; q++) {
        int j = t + 256 * q;            // 2048 uint4 = 256 rows * 8
        int n = j >> 3, c = j & 7;
        *(uint4*)&Ws[n * 72 + c * 8] = ((const uint4*)g_WhT)[j];
    }
    // load + convert A tile
#pragma unroll
    for (int q = 0; q < 2; q++) {
        int i = t + 256 * q;            // 512 float4 = 32 rows * 16
        int r = i >> 4, c4 = (i & 15) * 4;
        int node = n0 + r;
        float4 hv = (node < N_NODES) ? *(const float4*)&h[node * 64 + c4]
                                     : make_float4(0.f, 0.f, 0.f, 0.f);
        __half2 p0 = __floats2half2_rn(hv.x, hv.y);
        __half2 p1 = __floats2half2_rn(hv.z, hv.w);
        uint2 pk = {*(unsigned*)&p0, *(unsigned*)&p1};
        *(uint2*)&As[r * 72 + c4] = pk;
    }
    __syncthreads();

    int rt = w & 1, cg = w >> 1;        // row tile (16 rows), col group (= head)
    int rbase = rt * 16;
    int qr = lane >> 2, qc = lane & 3;

    float acc[8][4];
#pragma unroll
    for (int i = 0; i < 8; i++)
#pragma unroll
        for (int j = 0; j < 4; j++) acc[i][j] = 0.f;

#pragma unroll
    for (int ks = 0; ks < 4; ks++) {
        int kk = ks * 16;
        unsigned a0 = *(const unsigned*)&As[(rbase + qr) * 72 + kk + 2 * qc];
        unsigned a1 = *(const unsigned*)&As[(rbase + qr + 8) * 72 + kk + 2 * qc];
        unsigned a2 = *(const unsigned*)&As[(rbase + qr) * 72 + kk + 8 + 2 * qc];
        unsigned a3 = *(const unsigned*)&As[(rbase + qr + 8) * 72 + kk + 8 + 2 * qc];
#pragma unroll
        for (int nf = 0; nf < 8; nf++) {
            int n = cg * 64 + nf * 8 + qr;
            unsigned b0 = *(const unsigned*)&Ws[n * 72 + kk + 2 * qc];
            unsigned b1 = *(const unsigned*)&Ws[n * 72 + kk + 8 + 2 * qc];
            mma16816(acc[nf], a0, a1, a2, a3, b0, b1);
        }
    }

    // epilogue: store x (fp16) + fused attention dot-products
    int node_lo = n0 + rbase + qr;
    int node_hi = node_lo + 8;
    float ps_lo = 0.f, ps_hi = 0.f, pd_lo = 0.f, pd_hi = 0.f;
#pragma unroll
    for (int nf = 0; nf < 8; nf++) {
        int col = cg * 64 + nf * 8 + 2 * qc;
        float2 sv = *(const float2*)&att_src[col];
        float2 dv = *(const float2*)&att_dst[col];
        ps_lo += acc[nf][0] * sv.x + acc[nf][1] * sv.y;
        ps_hi += acc[nf][2] * sv.x + acc[nf][3] * sv.y;
        pd_lo += acc[nf][0] * dv.x + acc[nf][1] * dv.y;
        pd_hi += acc[nf][2] * dv.x + acc[nf][3] * dv.y;
        if (node_lo < N_NODES)
            g_x2[node_lo * 128 + cg * 32 + nf * 4 + qc] = __floats2half2_rn(acc[nf][0], acc[nf][1]);
        if (node_hi < N_NODES)
            g_x2[node_hi * 128 + cg * 32 + nf * 4 + qc] = __floats2half2_rn(acc[nf][2], acc[nf][3]);
    }
    ps_lo += __shfl_xor_sync(0xffffffffu, ps_lo, 1);
    ps_lo += __shfl_xor_sync(0xffffffffu, ps_lo, 2);
    ps_hi += __shfl_xor_sync(0xffffffffu, ps_hi, 1);
    ps_hi += __shfl_xor_sync(0xffffffffu, ps_hi, 2);
    pd_lo += __shfl_xor_sync(0xffffffffu, pd_lo, 1);
    pd_lo += __shfl_xor_sync(0xffffffffu, pd_lo, 2);
    pd_hi += __shfl_xor_sync(0xffffffffu, pd_hi, 1);
    pd_hi += __shfl_xor_sync(0xffffffffu, pd_hi, 2);
    if (qc == 0) {
        if (node_lo < N_NODES) { g_asrc[node_lo * 4 + cg] = ps_lo; g_adst[node_lo * 4 + cg] = pd_lo; }
        if (node_hi < N_NODES) { g_asrc[node_hi * 4 + cg] = ps_hi; g_adst[node_hi * 4 + cg] = pd_hi; }
    }
}

// ---------------- scatter: sorted {alpha4, src} per dst ----------------
__global__ void k_scatter(const float* __restrict__ attr) {
    int e = blockIdx.x * blockDim.x + threadIdx.x;
    if (e >= N_EDGES) return;
    int s = g_src[e], d = g_dst[e];
    float a0 = attr[e * 3 + 0], a1 = attr[e * 3 + 1], a2 = attr[e * 3 + 2];
    float4 as = *(const float4*)&g_asrc[s * 4];
    float4 ad = *(const float4*)&g_adst[d * 4];
    float base[4] = {as.x + ad.x, as.y + ad.y, as.z + ad.z, as.w + ad.w};
    float4 outv;
    float* po = &outv.x;
#pragma unroll
    for (int hh = 0; hh < 4; hh++) {
        float a = base[hh] + a0 * g_v[hh] + a1 * g_v[4 + hh] + a2 * g_v[8 + hh];
        po[hh] = a > 0.0f ? a : 0.2f * a;
    }
    int pos = atomicAdd(&g_cur[d], 1);
    *(float4*)&g_salpha[pos * 4] = outv;
    g_ssrc[pos] = s;
}

// ---------------- warp per node: softmax + fp16 gather + LN + SiLU ----------------
__global__ void __launch_bounds__(256) k_node(float* __restrict__ out,
                                              const float* __restrict__ bias,
                                              const float* __restrict__ gamma,
                                              const float* __restrict__ beta) {
    int t = threadIdx.x, lane = t & 31, w = t >> 5;
    int n = blockIdx.x * 8 + w;
    int beg = g_off[n], end = g_off[n + 1];
    const float4* sal = (const float4*)g_salpha;

    // pass 1: segment max per head
    const float NINF = __int_as_float(0xff800000);
    float4 m = {NINF, NINF, NINF, NINF};
    for (int k = beg + lane; k < end; k += 32) {
        float4 a = sal[k];
        m.x = fmaxf(m.x, a.x); m.y = fmaxf(m.y, a.y);
        m.z = fmaxf(m.z, a.z); m.w = fmaxf(m.w, a.w);
    }
#pragma unroll
    for (int o = 16; o; o >>= 1) {
        m.x = fmaxf(m.x, __shfl_xor_sync(0xffffffffu, m.x, o));
        m.y = fmaxf(m.y, __shfl_xor_sync(0xffffffffu, m.y, o));
        m.z = fmaxf(m.z, __shfl_xor_sync(0xffffffffu, m.z, o));
        m.w = fmaxf(m.w, __shfl_xor_sync(0xffffffffu, m.w, o));
    }

    // pass 2: sum of exp
    float4 sm = {0.f, 0.f, 0.f, 0.f};
    for (int k = beg + lane; k < end; k += 32) {
        float4 a = sal[k];
        sm.x += expf(a.x - m.x); sm.y += expf(a.y - m.y);
        sm.z += expf(a.z - m.z); sm.w += expf(a.w - m.w);
    }
#pragma unroll
    for (int o = 16; o; o >>= 1) {
        sm.x += __shfl_xor_sync(0xffffffffu, sm.x, o);
        sm.y += __shfl_xor_sync(0xffffffffu, sm.y, o);
        sm.z += __shfl_xor_sync(0xffffffffu, sm.z, o);
        sm.w += __shfl_xor_sync(0xffffffffu, sm.w, o);
    }

    // per-lane head constants
    int hd = lane >> 3;   // head for this lane's 8 channels
    float mh = (hd == 0) ? m.x : (hd == 1) ? m.y : (hd == 2) ? m.z : m.w;
    float sh = (hd == 0) ? sm.x : (hd == 1) ? sm.y : (hd == 2) ? sm.z : sm.w;
    float ih = 0.25f / (sh + 1e-16f);

    // pass 3: weighted gather of fp16 x; lane covers halfs [8*lane, 8*lane+8)
    float acc[8];
#pragma unroll
    for (int i = 0; i < 8; i++) acc[i] = 0.f;
    const uint4* xv4 = (const uint4*)g_x2;
    for (int k = beg; k < end; k++) {
        float4 a = sal[k];                        // broadcast
        int s = g_ssrc[k];                        // broadcast
        float ah = (hd == 0) ? a.x : (hd == 1) ? a.y : (hd == 2) ? a.z : a.w;
        float wgt = expf(ah - mh) * ih;
        uint4 xv = xv4[s * 32 + lane];
        const __half2* hp = (const __half2*)&xv;
#pragma unroll
        for (int i = 0; i < 4; i++) {
            float2 f = __half22float2(hp[i]);
            acc[2 * i]     += wgt * f.x;
            acc[2 * i + 1] += wgt * f.y;
        }
    }
    // fold the 4 head groups: lanes with same (lane&7) share channels
#pragma unroll
    for (int i = 0; i < 8; i++) {
        acc[i] += __shfl_xor_sync(0xffffffffu, acc[i], 8);
        acc[i] += __shfl_xor_sync(0xffffffffu, acc[i], 16);
    }

    // LN + SiLU over 64 channels held by lanes 0..7 (replicated in all lanes)
    int j = lane & 7;     // channel group: chans 8j..8j+7
    float4 b0 = ((const float4*)bias)[2 * j];
    float4 b1 = ((const float4*)bias)[2 * j + 1];
    float v[8] = {acc[0] + b0.x, acc[1] + b0.y, acc[2] + b0.z, acc[3] + b0.w,
                  acc[4] + b1.x, acc[5] + b1.y, acc[6] + b1.z, acc[7] + b1.w};
    float sum = 0.f, sq = 0.f;
#pragma unroll
    for (int i = 0; i < 8; i++) { sum += v[i]; sq += v[i] * v[i]; }
#pragma unroll
    for (int o = 4; o; o >>= 1) {
        sum += __shfl_xor_sync(0xffffffffu, sum, o);
        sq  += __shfl_xor_sync(0xffffffffu, sq, o);
    }
    float mu  = sum * (1.0f / 64.0f);
    float var = sq * (1.0f / 64.0f) - mu * mu;
    float inv = rsqrtf(var + 1e-5f);
    float4 g0 = ((const float4*)gamma)[2 * j];
    float4 g1 = ((const float4*)gamma)[2 * j + 1];
    float4 e0 = ((const float4*)beta)[2 * j];
    float4 e1 = ((const float4*)beta)[2 * j + 1];
    float gg[8] = {g0.x, g0.y, g0.z, g0.w, g1.x, g1.y, g1.z, g1.w};
    float ee[8] = {e0.x, e0.y, e0.z, e0.w, e1.x, e1.y, e1.z, e1.w};
    float y[8];
#pragma unroll
    for (int i = 0; i < 8; i++) {
        float yy = (v[i] - mu) * inv * gg[i] + ee[i];
        y[i] = yy / (1.0f + expf(-yy));
    }
    if (lane < 8) {
        float4 o0 = {y[0], y[1], y[2], y[3]};
        float4 o1 = {y[4], y[5], y[6], y[7]};
        ((float4*)out)[n * 16 + 2 * j]     = o0;
        ((float4*)out)[n * 16 + 2 * j + 1] = o1;
    }
}

extern "C" void kernel_launch(void* const* d_in, const int* in_sizes, int n_in,
                              void* d_out, int out_size) {
    // order: t, h, edge_index, edge_attr, W, att_src, att_dst,
    //        W_edge, att_edge, bias, ln_gamma, ln_beta
    const float* h        = (const float*)d_in[1];
    const void*  ei       = d_in[2];
    const float* attr     = (const float*)d_in[3];
    const float* W        = (const float*)d_in[4];
    const float* att_src  = (const float*)d_in[5];
    const float* att_dst  = (const float*)d_in[6];
    const float* W_edge   = (const float*)d_in[7];
    const float* att_edge = (const float*)d_in[8];
    const float* bias     = (const float*)d_in[9];
    const float* gamma    = (const float*)d_in[10];
    const float* beta     = (const float*)d_in[11];
    float* out = (float*)d_out;

    k_init   <<<197, 256>>>((const unsigned*)ei);
    k_prep   <<<(N_EDGES + 255) / 256, 256>>>(ei);
    k_scan1  <<<NB_SCAN, 1024>>>();
    k_scan2  <<<1, 64>>>();
    k_scan3  <<<NB_SCAN, 1024>>>();
    k_wconv  <<<65, 256>>>(W, W_edge, att_edge);
    k_gemm   <<<(N_NODES + 31) / 32, 256>>>(h, att_src, att_dst);
    k_scatter<<<(N_EDGES + 255) / 256, 256>>>(attr);
    k_node   <<<N_NODES / 8, 256>>>(out, bias, gamma, beta);
}